// round 9
// baseline (speedup 1.0000x reference)
#include <cuda_runtime.h>
#include <cuda_bf16.h>
#include <mma.h>
#include <cstddef>

using namespace nvcuda;

#define Bc 4
#define Sc 1024
#define Dc 1024
#define Hc 16
#define DKc 64
#define DVc 64
#define Mc (Bc * Sc)
#define HDc (Hc * DKc)
#define QP_ELEMS (Mc * HDc)

// ---------------- Static device scratch ----------------
__device__ __nv_bfloat16 g_Qph[QP_ELEMS], g_Qpl[QP_ELEMS];   // [B,H,S,64] hi/lo
__device__ __nv_bfloat16 g_Kph[QP_ELEMS], g_Kpl[QP_ELEMS];
__device__ __nv_bfloat16 g_Vp[QP_ELEMS];                     // [B,H,S,64]
__device__ __nv_bfloat16 g_ctx[Mc * HDc];                    // [B,S,1024]
__device__ __nv_bfloat16 g_attn_bf[(size_t)Bc * Hc * Sc * Sc]; // bf16 probs
__device__ float g_obuf[Mc * Dc];
__device__ float g_attn_fb[(size_t)Bc * Hc * Sc * Sc];
__device__ int   g_mask_mode;

using bfrag_a  = wmma::fragment<wmma::matrix_a, 16, 16, 16, __nv_bfloat16, wmma::row_major>;
using bfrag_b  = wmma::fragment<wmma::matrix_b, 16, 16, 16, __nv_bfloat16, wmma::row_major>;
using bfrag_bc = wmma::fragment<wmma::matrix_b, 16, 16, 16, __nv_bfloat16, wmma::col_major>;
using bfrag_c  = wmma::fragment<wmma::accumulator, 16, 16, 16, float>;

__device__ __forceinline__ void cvt_store4(__nv_bfloat16* dh, __nv_bfloat16* dl, float4 v) {
    float a[4] = {v.x, v.y, v.z, v.w};
#pragma unroll
    for (int j = 0; j < 4; j++) {
        __nv_bfloat16 h = __float2bfloat16(a[j]);
        dh[j] = h;
        dl[j] = __float2bfloat16(a[j] - __bfloat162float(h));
    }
}

__device__ __forceinline__ void cvt_store4_s(__nv_bfloat16* dh, float4 v) {
    dh[0] = __float2bfloat16(v.x);
    dh[1] = __float2bfloat16(v.y);
    dh[2] = __float2bfloat16(v.z);
    dh[3] = __float2bfloat16(v.w);
}

// ---------------------------------------------------------------------------
__global__ void detect_mask_kernel(const unsigned int* __restrict__ m) {
    bool allint = true, allfloat = true;
    for (int i = 0; i < 1024; i++) {
        unsigned int w = m[i];
        if (w > 1u) allint = false;
        if (w != 0u && w != 0x3F800000u) allfloat = false;
    }
    g_mask_mode = allint ? 0 : (allfloat ? 2 : 1);
}

// ---------------------------------------------------------------------------
// Merged QKV projection: grid z = 0(Q,split), 1(K,split), 2(V,single).
// BM=128, BN=128, BK=16, warp tile 32x64, double-buffered smem.
// ---------------------------------------------------------------------------
__global__ __launch_bounds__(256)
void qkv_proj(const float* __restrict__ q, const float* __restrict__ k,
              const float* __restrict__ v,
              const float* __restrict__ Wq, const float* __restrict__ Wk,
              const float* __restrict__ Wv,
              const float* __restrict__ bq, const float* __restrict__ bk,
              const float* __restrict__ bv,
              __nv_bfloat16* __restrict__ Qph, __nv_bfloat16* __restrict__ Qpl,
              __nv_bfloat16* __restrict__ Kph, __nv_bfloat16* __restrict__ Kpl,
              __nv_bfloat16* __restrict__ Vp) {
    constexpr int LDA = 24;
    constexpr int LDW = 136;
    constexpr int LDST = 132;

    __shared__ __align__(16) char buf[41984];
    __nv_bfloat16* Ahi = (__nv_bfloat16*)buf;        // [2][128][24]
    __nv_bfloat16* Alo = Ahi + 2 * 128 * LDA;
    __nv_bfloat16* Whi = Alo + 2 * 128 * LDA;        // [2][16][136]
    __nv_bfloat16* Wlo = Whi + 2 * 16 * LDW;
    float* stg = (float*)buf;

    const int z = blockIdx.z;
    const bool SPLIT = (z < 2);
    const float* A    = (z == 0) ? q  : (z == 1) ? k  : v;
    const float* W    = (z == 0) ? Wq : (z == 1) ? Wk : Wv;
    const float* bias = (z == 0) ? bq : (z == 1) ? bk : bv;
    __nv_bfloat16* Ch = (z == 0) ? Qph : Kph;
    __nv_bfloat16* Cl = (z == 0) ? Qpl : Kpl;

    const int tid = threadIdx.x;
    const int w = tid >> 5;
    const int wm = w >> 1;
    const int wn = w & 1;
    const int row0 = blockIdx.y * 128;
    const int col0 = blockIdx.x * 128;

    const int ar = tid >> 2, ac = (tid & 3) * 4;
    const int wr0 = tid >> 5, wc0 = (tid & 31) * 4;

    bfrag_c acc[2][4];
#pragma unroll
    for (int ti = 0; ti < 2; ti++)
#pragma unroll
        for (int tj = 0; tj < 4; tj++) wmma::fill_fragment(acc[ti][tj], 0.0f);

    float4 ra0, ra1, rw0, rw1;
    ra0 = *(const float4*)&A[(size_t)(row0 + ar) * Dc + ac];
    ra1 = *(const float4*)&A[(size_t)(row0 + ar + 64) * Dc + ac];
    rw0 = *(const float4*)&W[(size_t)wr0 * HDc + col0 + wc0];
    rw1 = *(const float4*)&W[(size_t)(wr0 + 8) * HDc + col0 + wc0];
    if (SPLIT) {
        cvt_store4(Ahi + ar * LDA + ac, Alo + ar * LDA + ac, ra0);
        cvt_store4(Ahi + (ar + 64) * LDA + ac, Alo + (ar + 64) * LDA + ac, ra1);
        cvt_store4(Whi + wr0 * LDW + wc0, Wlo + wr0 * LDW + wc0, rw0);
        cvt_store4(Whi + (wr0 + 8) * LDW + wc0, Wlo + (wr0 + 8) * LDW + wc0, rw1);
    } else {
        cvt_store4_s(Ahi + ar * LDA + ac, ra0);
        cvt_store4_s(Ahi + (ar + 64) * LDA + ac, ra1);
        cvt_store4_s(Whi + wr0 * LDW + wc0, rw0);
        cvt_store4_s(Whi + (wr0 + 8) * LDW + wc0, rw1);
    }
    __syncthreads();

    for (int kt = 0; kt < 64; kt++) {
        if (kt < 63) {
            int kk = (kt + 1) * 16;
            ra0 = *(const float4*)&A[(size_t)(row0 + ar) * Dc + kk + ac];
            ra1 = *(const float4*)&A[(size_t)(row0 + ar + 64) * Dc + kk + ac];
            rw0 = *(const float4*)&W[(size_t)(kk + wr0) * HDc + col0 + wc0];
            rw1 = *(const float4*)&W[(size_t)(kk + wr0 + 8) * HDc + col0 + wc0];
        }
        const int cur = kt & 1;
        const int cb = cur * 128 * LDA;
        const int wb = cur * 16 * LDW;

        bfrag_a fah[2], fal[2];
#pragma unroll
        for (int ti = 0; ti < 2; ti++) {
            wmma::load_matrix_sync(fah[ti], Ahi + cb + (wm * 32 + ti * 16) * LDA, LDA);
            if (SPLIT)
                wmma::load_matrix_sync(fal[ti], Alo + cb + (wm * 32 + ti * 16) * LDA, LDA);
        }
#pragma unroll
        for (int tj = 0; tj < 4; tj++) {
            bfrag_b fbh, fbl;
            wmma::load_matrix_sync(fbh, Whi + wb + wn * 64 + tj * 16, LDW);
            if (SPLIT) wmma::load_matrix_sync(fbl, Wlo + wb + wn * 64 + tj * 16, LDW);
#pragma unroll
            for (int ti = 0; ti < 2; ti++) {
                wmma::mma_sync(acc[ti][tj], fah[ti], fbh, acc[ti][tj]);
                if (SPLIT) {
                    wmma::mma_sync(acc[ti][tj], fah[ti], fbl, acc[ti][tj]);
                    wmma::mma_sync(acc[ti][tj], fal[ti], fbh, acc[ti][tj]);
                }
            }
        }

        if (kt < 63) {
            const int nb = (cur ^ 1) * 128 * LDA;
            const int nw = (cur ^ 1) * 16 * LDW;
            if (SPLIT) {
                cvt_store4(Ahi + nb + ar * LDA + ac, Alo + nb + ar * LDA + ac, ra0);
                cvt_store4(Ahi + nb + (ar + 64) * LDA + ac, Alo + nb + (ar + 64) * LDA + ac, ra1);
                cvt_store4(Whi + nw + wr0 * LDW + wc0, Wlo + nw + wr0 * LDW + wc0, rw0);
                cvt_store4(Whi + nw + (wr0 + 8) * LDW + wc0, Wlo + nw + (wr0 + 8) * LDW + wc0, rw1);
            } else {
                cvt_store4_s(Ahi + nb + ar * LDA + ac, ra0);
                cvt_store4_s(Ahi + nb + (ar + 64) * LDA + ac, ra1);
                cvt_store4_s(Whi + nw + wr0 * LDW + wc0, rw0);
                cvt_store4_s(Whi + nw + (wr0 + 8) * LDW + wc0, rw1);
            }
        }
        __syncthreads();
    }

#pragma unroll
    for (int ph = 0; ph < 2; ph++) {
        if ((wm >> 1) == ph) {
#pragma unroll
            for (int ti = 0; ti < 2; ti++)
#pragma unroll
                for (int tj = 0; tj < 4; tj++)
                    wmma::store_matrix_sync(&stg[((wm & 1) * 32 + ti * 16) * LDST + wn * 64 + tj * 16],
                                            acc[ti][tj], LDST, wmma::mem_row_major);
        }
        __syncthreads();
#pragma unroll
        for (int i = tid; i < 2048; i += 256) {
            int r = i >> 5, c4 = (i & 31) * 4;
            int m = row0 + ph * 64 + r;
            int col = col0 + c4;
            float4 vv = *(float4*)&stg[r * LDST + c4];
            float4 bi = *(const float4*)&bias[col];
            vv.x += bi.x; vv.y += bi.y; vv.z += bi.z; vv.w += bi.w;
            int b = m >> 10, s = m & 1023, h = col >> 6, d = col & 63;
            size_t o = (((size_t)b * Hc + h) * Sc + s) * 64 + d;
            if (SPLIT) cvt_store4(Ch + o, Cl + o, vv);
            else       cvt_store4_s(Vp + o, vv);
        }
        __syncthreads();
    }
}

// ---------------------------------------------------------------------------
// Scores from planes: 64x64 tile per block, split-bf16, mask -> raw scores.
// High occupancy (36KB smem). Proven R7 version.
// ---------------------------------------------------------------------------
__global__ __launch_bounds__(256)
void scores_planes(const __nv_bfloat16* __restrict__ Qh, const __nv_bfloat16* __restrict__ Ql,
                   const __nv_bfloat16* __restrict__ Kh, const __nv_bfloat16* __restrict__ Kl,
                   const void* __restrict__ mask, float* __restrict__ attn) {
    constexpr int LDT = 72;
    constexpr int LDST = 68;

    __shared__ __align__(16) char buf[36864];
    __nv_bfloat16* Qhi = (__nv_bfloat16*)buf;
    __nv_bfloat16* Qlo = Qhi + 64 * LDT;
    __nv_bfloat16* Khi = Qlo + 64 * LDT;
    __nv_bfloat16* Klo = Khi + 64 * LDT;
    float* stg = (float*)buf;

    const int z = blockIdx.z;
    const int b = z >> 4;
    const int q0 = blockIdx.y * 64;
    const int k0 = blockIdx.x * 64;
    const int tid = threadIdx.x;
    const int w = tid >> 5;
    const int wm = w & 1;
    const int wn = w >> 1;

    const size_t zb = (size_t)z * Sc * 64;

#pragma unroll
    for (int i = tid; i < 512; i += 256) {
        int r = i >> 3, c = (i & 7) * 8;
        *(uint4*)&Qhi[r * LDT + c] = *(const uint4*)&Qh[zb + (size_t)(q0 + r) * 64 + c];
        *(uint4*)&Qlo[r * LDT + c] = *(const uint4*)&Ql[zb + (size_t)(q0 + r) * 64 + c];
        *(uint4*)&Khi[r * LDT + c] = *(const uint4*)&Kh[zb + (size_t)(k0 + r) * 64 + c];
        *(uint4*)&Klo[r * LDT + c] = *(const uint4*)&Kl[zb + (size_t)(k0 + r) * 64 + c];
    }
    __syncthreads();

    bfrag_c acc[2];
    wmma::fill_fragment(acc[0], 0.0f);
    wmma::fill_fragment(acc[1], 0.0f);

#pragma unroll
    for (int ks = 0; ks < 4; ks++) {
        const int kb = ks * 16;
        bfrag_a fah[2], fal[2];
#pragma unroll
        for (int ti = 0; ti < 2; ti++) {
            wmma::load_matrix_sync(fah[ti], Qhi + (wm * 32 + ti * 16) * LDT + kb, LDT);
            wmma::load_matrix_sync(fal[ti], Qlo + (wm * 32 + ti * 16) * LDT + kb, LDT);
        }
        bfrag_bc fbh, fbl;
        wmma::load_matrix_sync(fbh, Khi + (wn * 16) * LDT + kb, LDT);
        wmma::load_matrix_sync(fbl, Klo + (wn * 16) * LDT + kb, LDT);
#pragma unroll
        for (int ti = 0; ti < 2; ti++) {
            wmma::mma_sync(acc[ti], fah[ti], fbh, acc[ti]);
            wmma::mma_sync(acc[ti], fah[ti], fbl, acc[ti]);
            wmma::mma_sync(acc[ti], fal[ti], fbh, acc[ti]);
        }
    }
    __syncthreads();
#pragma unroll
    for (int ti = 0; ti < 2; ti++)
        wmma::store_matrix_sync(&stg[(wm * 32 + ti * 16) * LDST + wn * 16], acc[ti],
                                LDST, wmma::mem_row_major);
    __syncthreads();

    const int mode = g_mask_mode;
    const int* mi = (const int*)mask;
    const unsigned char* mb8 = (const unsigned char*)mask;
    const float* mf = (const float*)mask;

#pragma unroll
    for (int i = tid; i < 4096; i += 256) {
        int r = i >> 6, c = i & 63;
        int qq = q0 + r, kk = k0 + c;
        size_t midx = (size_t)b * Sc * Sc + (size_t)qq * Sc + kk;
        bool masked;
        if (mode == 0)      masked = (mi[midx] != 0);
        else if (mode == 2) masked = (mf[midx] != 0.0f);
        else                masked = (mb8[midx] != 0);
        float v = masked ? -1e9f : stg[r * LDST + c] * 0.125f;
        attn[((size_t)z * Sc + qq) * Sc + kk] = v;
    }
}

// ---------------------------------------------------------------------------
// Row softmax, in place; also emits bf16 copy of probs for the context GEMM.
// ---------------------------------------------------------------------------
__global__ __launch_bounds__(256)
void softmax_kernel(float* __restrict__ attn, __nv_bfloat16* __restrict__ attn_bf) {
    const size_t row = blockIdx.x;
    float4* p = (float4*)(attn + row * Sc);
    __nv_bfloat16* pb = attn_bf + row * Sc;
    const int tid = threadIdx.x;
    const int lane = tid & 31, wid = tid >> 5;
    __shared__ float sm[16];

    float4 v = p[tid];
    float mx = fmaxf(fmaxf(v.x, v.y), fmaxf(v.z, v.w));
#pragma unroll
    for (int o = 16; o; o >>= 1) mx = fmaxf(mx, __shfl_xor_sync(0xffffffffu, mx, o));
    if (lane == 0) sm[wid] = mx;
    __syncthreads();
    float m = sm[0];
#pragma unroll
    for (int i = 1; i < 8; i++) m = fmaxf(m, sm[i]);

    v.x = expf(v.x - m); v.y = expf(v.y - m);
    v.z = expf(v.z - m); v.w = expf(v.w - m);
    float s = (v.x + v.y) + (v.z + v.w);
#pragma unroll
    for (int o = 16; o; o >>= 1) s += __shfl_xor_sync(0xffffffffu, s, o);
    if (lane == 0) sm[8 + wid] = s;
    __syncthreads();
    float tot = 0.0f;
#pragma unroll
    for (int i = 0; i < 8; i++) tot += sm[8 + i];
    float inv = 1.0f / tot;
    v.x *= inv; v.y *= inv; v.z *= inv; v.w *= inv;
    p[tid] = v;
    cvt_store4_s(pb + tid * 4, v);
}

// ---------------------------------------------------------------------------
// Context: BM=128, BN=64, warp tile 32x32 (4x2 warps). Small smem (~17KB)
// for high occupancy. A = bf16 probs, B = V plane. Out: bf16 ctx concat.
// ---------------------------------------------------------------------------
__global__ __launch_bounds__(256)
void context_128(const __nv_bfloat16* __restrict__ P, const __nv_bfloat16* __restrict__ Vp,
                 __nv_bfloat16* __restrict__ C) {
    constexpr int LDA = 24;
    constexpr int LDW = 72;
    constexpr int LDST = 68;

    __shared__ __align__(16) char buf[17408];
    __nv_bfloat16* As = (__nv_bfloat16*)buf;         // [2][128][24]
    __nv_bfloat16* Ws = As + 2 * 128 * LDA;          // [2][16][72]
    float* stg = (float*)buf;                        // [64][68] epilogue reuse

    const int tid = threadIdx.x;
    const int w = tid >> 5;
    const int wm = w >> 1;      // 0..3
    const int wn = w & 1;       // 0..1
    const int z = blockIdx.y;
    const int row0 = blockIdx.x * 128;

    const __nv_bfloat16* Pb = P + (size_t)z * Sc * Sc;
    const __nv_bfloat16* Vb = Vp + (size_t)z * Sc * 64;

    const int ar = tid >> 1, ac = (tid & 1) * 8;     // A: 128x16 -> 1 uint4/thread
    const int in_b = tid < 128;
    const int wr = tid >> 3, wc = (tid & 7) * 8;     // B: 16x64 -> tid<128

    bfrag_c acc[2][2];
#pragma unroll
    for (int ti = 0; ti < 2; ti++)
#pragma unroll
        for (int tj = 0; tj < 2; tj++) wmma::fill_fragment(acc[ti][tj], 0.0f);

    uint4 pa, pb;
    pa = *(const uint4*)&Pb[(size_t)(row0 + ar) * Sc + ac];
    if (in_b) pb = *(const uint4*)&Vb[(size_t)wr * 64 + wc];
    *(uint4*)&As[ar * LDA + ac] = pa;
    if (in_b) *(uint4*)&Ws[wr * LDW + wc] = pb;
    __syncthreads();

    for (int kt = 0; kt < 64; kt++) {
        if (kt < 63) {
            int kk = (kt + 1) * 16;
            pa = *(const uint4*)&Pb[(size_t)(row0 + ar) * Sc + kk + ac];
            if (in_b) pb = *(const uint4*)&Vb[(size_t)(kk + wr) * 64 + wc];
        }
        const int cur = kt & 1;
        const int cb = cur * 128 * LDA;
        const int wb = cur * 16 * LDW;

        bfrag_a fa[2];
#pragma unroll
        for (int ti = 0; ti < 2; ti++)
            wmma::load_matrix_sync(fa[ti], As + cb + (wm * 32 + ti * 16) * LDA, LDA);
#pragma unroll
        for (int tj = 0; tj < 2; tj++) {
            bfrag_b fb;
            wmma::load_matrix_sync(fb, Ws + wb + wn * 32 + tj * 16, LDW);
#pragma unroll
            for (int ti = 0; ti < 2; ti++)
                wmma::mma_sync(acc[ti][tj], fa[ti], fb, acc[ti][tj]);
        }

        if (kt < 63) {
            const int nb = (cur ^ 1) * 128 * LDA;
            const int nw = (cur ^ 1) * 16 * LDW;
            *(uint4*)&As[nb + ar * LDA + ac] = pa;
            if (in_b) *(uint4*)&Ws[nw + wr * LDW + wc] = pb;
        }
        __syncthreads();
    }

    const int b = z >> 4, h = z & 15;
#pragma unroll
    for (int ph = 0; ph < 2; ph++) {
        if ((wm >> 1) == ph) {
#pragma unroll
            for (int ti = 0; ti < 2; ti++)
#pragma unroll
                for (int tj = 0; tj < 2; tj++)
                    wmma::store_matrix_sync(&stg[((wm & 1) * 32 + ti * 16) * LDST + wn * 32 + tj * 16],
                                            acc[ti][tj], LDST, wmma::mem_row_major);
        }
        __syncthreads();
#pragma unroll
        for (int i = tid; i < 1024; i += 256) {
            int r = i >> 4, c4 = (i & 15) * 4;
            int s = row0 + ph * 64 + r;
            float4 vv = *(float4*)&stg[r * LDST + c4];
            cvt_store4_s(C + ((size_t)(b * Sc + s)) * HDc + h * DVc + c4, vv);
        }
        __syncthreads();
    }
}

// ---------------------------------------------------------------------------
// Out-proj: BM=128, BN=64, warp tile 32x32 (4x2 warps), small smem.
// A = ctx bf16 plane (raw loads), W fp32 (cvt in-loop), fp32 out (+bias).
// ---------------------------------------------------------------------------
__global__ __launch_bounds__(256)
void outproj_128(const __nv_bfloat16* __restrict__ Ab, const float* __restrict__ W,
                 const float* __restrict__ bias, float* __restrict__ Cf) {
    constexpr int LDA = 24;
    constexpr int LDW = 72;
    constexpr int LDST = 68;

    __shared__ __align__(16) char buf[17408];
    __nv_bfloat16* As = (__nv_bfloat16*)buf;         // [2][128][24]
    __nv_bfloat16* Ws = As + 2 * 128 * LDA;          // [2][16][72]
    float* stg = (float*)buf;                        // [64][68]

    const int tid = threadIdx.x;
    const int w = tid >> 5;
    const int wm = w >> 1;
    const int wn = w & 1;
    const int row0 = blockIdx.y * 128;
    const int col0 = blockIdx.x * 64;

    const int ar = tid >> 1, ac = (tid & 1) * 8;
    const int wr = tid >> 4, wc = (tid & 15) * 4;    // W: 16x64 fp32 -> 1 float4/thread

    bfrag_c acc[2][2];
#pragma unroll
    for (int ti = 0; ti < 2; ti++)
#pragma unroll
        for (int tj = 0; tj < 2; tj++) wmma::fill_fragment(acc[ti][tj], 0.0f);

    uint4 pa;
    float4 rw;
    pa = *(const uint4*)&Ab[(size_t)(row0 + ar) * Dc + ac];
    rw = *(const float4*)&W[(size_t)wr * Dc + col0 + wc];
    *(uint4*)&As[ar * LDA + ac] = pa;
    cvt_store4_s(Ws + wr * LDW + wc, rw);
    __syncthreads();

    for (int kt = 0; kt < 64; kt++) {
        if (kt < 63) {
            int kk = (kt + 1) * 16;
            pa = *(const uint4*)&Ab[(size_t)(row0 + ar) * Dc + kk + ac];
            rw = *(const float4*)&W[(size_t)(kk + wr) * Dc + col0 + wc];
        }
        const int cur = kt & 1;
        const int cb = cur * 128 * LDA;
        const int wb = cur * 16 * LDW;

        bfrag_a fa[2];
#pragma unroll
        for (int ti = 0; ti < 2; ti++)
            wmma::load_matrix_sync(fa[ti], As + cb + (wm * 32 + ti * 16) * LDA, LDA);
#pragma unroll
        for (int tj = 0; tj < 2; tj++) {
            bfrag_b fb;
            wmma::load_matrix_sync(fb, Ws + wb + wn * 32 + tj * 16, LDW);
#pragma unroll
            for (int ti = 0; ti < 2; ti++)
                wmma::mma_sync(acc[ti][tj], fa[ti], fb, acc[ti][tj]);
        }

        if (kt < 63) {
            const int nb = (cur ^ 1) * 128 * LDA;
            const int nw = (cur ^ 1) * 16 * LDW;
            *(uint4*)&As[nb + ar * LDA + ac] = pa;
            cvt_store4_s(Ws + nw + wr * LDW + wc, rw);
        }
        __syncthreads();
    }

#pragma unroll
    for (int ph = 0; ph < 2; ph++) {
        if ((wm >> 1) == ph) {
#pragma unroll
            for (int ti = 0; ti < 2; ti++)
#pragma unroll
                for (int tj = 0; tj < 2; tj++)
                    wmma::store_matrix_sync(&stg[((wm & 1) * 32 + ti * 16) * LDST + wn * 32 + tj * 16],
                                            acc[ti][tj], LDST, wmma::mem_row_major);
        }
        __syncthreads();
#pragma unroll
        for (int i = tid; i < 1024; i += 256) {
            int r = i >> 4, c4 = (i & 15) * 4;
            int m = row0 + ph * 64 + r;
            int col = col0 + c4;
            float4 vv = *(float4*)&stg[r * LDST + c4];
            float4 bi = *(const float4*)&bias[col];
            vv.x += bi.x; vv.y += bi.y; vv.z += bi.z; vv.w += bi.w;
            *(float4*)&Cf[(size_t)m * Dc + col] = vv;
        }
        __syncthreads();
    }
}

// ---------------------------------------------------------------------------
// Fused residual add + LayerNorm
// ---------------------------------------------------------------------------
__global__ __launch_bounds__(256)
void layernorm_kernel(const float* __restrict__ x, const float* __restrict__ resid,
                      float* __restrict__ out) {
    const size_t row = blockIdx.x;
    const float4* xr = (const float4*)(x + row * Dc);
    const float4* rr = (const float4*)(resid + row * Dc);
    float4* orow = (float4*)(out + row * Dc);
    const int tid = threadIdx.x;
    const int lane = tid & 31, wid = tid >> 5;
    __shared__ float sm[16];

    float4 a = xr[tid], b = rr[tid];
    float4 v = make_float4(a.x + b.x, a.y + b.y, a.z + b.z, a.w + b.w);
    float s = (v.x + v.y) + (v.z + v.w);
#pragma unroll
    for (int o = 16; o; o >>= 1) s += __shfl_xor_sync(0xffffffffu, s, o);
    if (lane == 0) sm[wid] = s;
    __syncthreads();
    float tot = 0.0f;
#pragma unroll
    for (int i = 0; i < 8; i++) tot += sm[i];
    float mean = tot * (1.0f / 1024.0f);

    float dx = v.x - mean, dy = v.y - mean, dz = v.z - mean, dw = v.w - mean;
    float vs = (dx * dx + dy * dy) + (dz * dz + dw * dw);
#pragma unroll
    for (int o = 16; o; o >>= 1) vs += __shfl_xor_sync(0xffffffffu, vs, o);
    if (lane == 0) sm[8 + wid] = vs;
    __syncthreads();
    float vtot = 0.0f;
#pragma unroll
    for (int i = 0; i < 8; i++) vtot += sm[8 + i];
    float inv = rsqrtf(vtot * (1.0f / 1024.0f) + 1e-5f);
    orow[tid] = make_float4(dx * inv, dy * inv, dz * inv, dw * inv);
}

// ---------------------------------------------------------------------------
// Launch
// ---------------------------------------------------------------------------
extern "C" void kernel_launch(void* const* d_in, const int* in_sizes, int n_in,
                              void* d_out, int out_size) {
    const float* q    = (const float*)d_in[0];
    const float* k    = (const float*)d_in[1];
    const float* v    = (const float*)d_in[2];
    const void*  mask = d_in[3];
    const float* Wq   = (const float*)d_in[4];
    const float* bq   = (const float*)d_in[5];
    const float* Wk   = (const float*)d_in[6];
    const float* bk   = (const float*)d_in[7];
    const float* Wv   = (const float*)d_in[8];
    const float* bv   = (const float*)d_in[9];
    const float* Wo   = (const float*)d_in[10];
    const float* bo   = (const float*)d_in[11];
    float* out = (float*)d_out;

    __nv_bfloat16 *Qph, *Qpl, *Kph, *Kpl, *Vp, *ctx, *attn_bf;
    float *obuf, *attn_fb;
    cudaGetSymbolAddress((void**)&Qph, g_Qph); cudaGetSymbolAddress((void**)&Qpl, g_Qpl);
    cudaGetSymbolAddress((void**)&Kph, g_Kph); cudaGetSymbolAddress((void**)&Kpl, g_Kpl);
    cudaGetSymbolAddress((void**)&Vp, g_Vp);
    cudaGetSymbolAddress((void**)&ctx, g_ctx);
    cudaGetSymbolAddress((void**)&attn_bf, g_attn_bf);
    cudaGetSymbolAddress((void**)&obuf, g_obuf);
    cudaGetSymbolAddress((void**)&attn_fb, g_attn_fb);

    const long long LN_ELEMS = (long long)Mc * Dc;
    const long long ATTN_ELEMS = (long long)Bc * Hc * Sc * Sc;
    float* attn = ((long long)out_size >= LN_ELEMS + ATTN_ELEMS)
                      ? (out + (size_t)LN_ELEMS)
                      : attn_fb;

    detect_mask_kernel<<<1, 1>>>((const unsigned int*)mask);

    // Merged QKV projections (z: 0=Q split, 1=K split, 2=V single)
    qkv_proj<<<dim3(8, 32, 3), 256>>>(q, k, v, Wq, Wk, Wv, bq, bk, bv,
                                      Qph, Qpl, Kph, Kpl, Vp);

    // Scores + mask -> raw scores (high occupancy)
    scores_planes<<<dim3(16, 16, Bc * Hc), 256>>>(Qph, Qpl, Kph, Kpl, mask, attn);

    // Softmax in place + bf16 probs copy
    softmax_kernel<<<Bc * Hc * Sc, 256>>>(attn, attn_bf);

    // Context (bf16 probs, high-occupancy tile) -> ctx bf16 plane
    context_128<<<dim3(8, 64), 256>>>(attn_bf, Vp, ctx);

    // Output projection (high-occupancy tile)
    outproj_128<<<dim3(16, 32), 256>>>(ctx, Wo, bo, obuf);

    // Residual + LayerNorm
    layernorm_kernel<<<Mc, 256>>>(obuf, q, out);
}

// round 12
// speedup vs baseline: 1.6360x; 1.6360x over previous
#include <cuda_runtime.h>
#include <cuda_fp16.h>
#include <mma.h>
#include <cstddef>

using namespace nvcuda;

#define Bc 4
#define Sc 1024
#define Dc 1024
#define Hc 16
#define DKc 64
#define DVc 64
#define Mc (Bc * Sc)
#define HDc (Hc * DKc)
#define QP_ELEMS (Mc * HDc)

// ---------------- Static device scratch (fp16) ----------------
__device__ __half g_Qp[QP_ELEMS];                    // [B,H,S,64]
__device__ __half g_Kp[QP_ELEMS];
__device__ __half g_Vp[QP_ELEMS];
__device__ __half g_ctx[Mc * HDc];                   // [B,S,1024]
__device__ __half g_attn_h[(size_t)Bc * Hc * Sc * Sc]; // fp16 probs
__device__ float g_obuf[Mc * Dc];
__device__ float g_attn_fb[(size_t)Bc * Hc * Sc * Sc];
__device__ int   g_mask_mode;

using hfrag_a  = wmma::fragment<wmma::matrix_a, 16, 16, 16, __half, wmma::row_major>;
using hfrag_b  = wmma::fragment<wmma::matrix_b, 16, 16, 16, __half, wmma::row_major>;
using hfrag_bc = wmma::fragment<wmma::matrix_b, 16, 16, 16, __half, wmma::col_major>;
using hfrag_c  = wmma::fragment<wmma::accumulator, 16, 16, 16, float>;

__device__ __forceinline__ void cvt_store4_h(__half* d, float4 v) {
    d[0] = __float2half(v.x);
    d[1] = __float2half(v.y);
    d[2] = __float2half(v.z);
    d[3] = __float2half(v.w);
}

// ---------------------------------------------------------------------------
__global__ void detect_mask_kernel(const unsigned int* __restrict__ m) {
    bool allint = true, allfloat = true;
    for (int i = 0; i < 1024; i++) {
        unsigned int w = m[i];
        if (w > 1u) allint = false;
        if (w != 0u && w != 0x3F800000u) allfloat = false;
    }
    g_mask_mode = allint ? 0 : (allfloat ? 2 : 1);
}

// ---------------------------------------------------------------------------
// Merged QKV projection (uniform single-fp16): grid z = 0(Q), 1(K), 2(V).
// BM=128, BN=128, BK=16, warp tile 32x64 (2x4), double-buffered smem.
// fp32 A,W in (cvt in-loop), epilogue +bias -> half plane [B,H,S,64].
// ---------------------------------------------------------------------------
__global__ __launch_bounds__(256)
void qkv_proj(const float* __restrict__ q, const float* __restrict__ k,
              const float* __restrict__ v,
              const float* __restrict__ Wq, const float* __restrict__ Wk,
              const float* __restrict__ Wv,
              const float* __restrict__ bq, const float* __restrict__ bk,
              const float* __restrict__ bv,
              __half* __restrict__ Qp, __half* __restrict__ Kp,
              __half* __restrict__ Vp) {
    constexpr int LDA = 24;
    constexpr int LDW = 136;
    constexpr int LDST = 132;

    __shared__ __align__(16) char buf[33792];
    __half* As = (__half*)buf;          // [2][128][24]
    __half* Ws = As + 2 * 128 * LDA;    // [2][16][136]
    float* stg = (float*)buf;           // [64][132] epilogue reuse

    const int z = blockIdx.z;
    const float* A    = (z == 0) ? q  : (z == 1) ? k  : v;
    const float* W    = (z == 0) ? Wq : (z == 1) ? Wk : Wv;
    const float* bias = (z == 0) ? bq : (z == 1) ? bk : bv;
    __half* C         = (z == 0) ? Qp : (z == 1) ? Kp : Vp;

    const int tid = threadIdx.x;
    const int w = tid >> 5;
    const int wm = w >> 1;      // 0..3
    const int wn = w & 1;       // 0..1
    const int row0 = blockIdx.y * 128;
    const int col0 = blockIdx.x * 128;

    const int ar = tid >> 2, ac = (tid & 3) * 4;
    const int wr0 = tid >> 5, wc0 = (tid & 31) * 4;

    hfrag_c acc[2][4];
#pragma unroll
    for (int ti = 0; ti < 2; ti++)
#pragma unroll
        for (int tj = 0; tj < 4; tj++) wmma::fill_fragment(acc[ti][tj], 0.0f);

    float4 ra0, ra1, rw0, rw1;
    ra0 = *(const float4*)&A[(size_t)(row0 + ar) * Dc + ac];
    ra1 = *(const float4*)&A[(size_t)(row0 + ar + 64) * Dc + ac];
    rw0 = *(const float4*)&W[(size_t)wr0 * HDc + col0 + wc0];
    rw1 = *(const float4*)&W[(size_t)(wr0 + 8) * HDc + col0 + wc0];
    cvt_store4_h(As + ar * LDA + ac, ra0);
    cvt_store4_h(As + (ar + 64) * LDA + ac, ra1);
    cvt_store4_h(Ws + wr0 * LDW + wc0, rw0);
    cvt_store4_h(Ws + (wr0 + 8) * LDW + wc0, rw1);
    __syncthreads();

    for (int kt = 0; kt < 64; kt++) {
        if (kt < 63) {
            int kk = (kt + 1) * 16;
            ra0 = *(const float4*)&A[(size_t)(row0 + ar) * Dc + kk + ac];
            ra1 = *(const float4*)&A[(size_t)(row0 + ar + 64) * Dc + kk + ac];
            rw0 = *(const float4*)&W[(size_t)(kk + wr0) * HDc + col0 + wc0];
            rw1 = *(const float4*)&W[(size_t)(kk + wr0 + 8) * HDc + col0 + wc0];
        }
        const int cur = kt & 1;
        const int cb = cur * 128 * LDA;
        const int wb = cur * 16 * LDW;

        hfrag_a fa[2];
#pragma unroll
        for (int ti = 0; ti < 2; ti++)
            wmma::load_matrix_sync(fa[ti], As + cb + (wm * 32 + ti * 16) * LDA, LDA);
#pragma unroll
        for (int tj = 0; tj < 4; tj++) {
            hfrag_b fb;
            wmma::load_matrix_sync(fb, Ws + wb + wn * 64 + tj * 16, LDW);
#pragma unroll
            for (int ti = 0; ti < 2; ti++)
                wmma::mma_sync(acc[ti][tj], fa[ti], fb, acc[ti][tj]);
        }

        if (kt < 63) {
            const int nb = (cur ^ 1) * 128 * LDA;
            const int nw = (cur ^ 1) * 16 * LDW;
            cvt_store4_h(As + nb + ar * LDA + ac, ra0);
            cvt_store4_h(As + nb + (ar + 64) * LDA + ac, ra1);
            cvt_store4_h(Ws + nw + wr0 * LDW + wc0, rw0);
            cvt_store4_h(Ws + nw + (wr0 + 8) * LDW + wc0, rw1);
        }
        __syncthreads();
    }

#pragma unroll
    for (int ph = 0; ph < 2; ph++) {
        if ((wm >> 1) == ph) {
#pragma unroll
            for (int ti = 0; ti < 2; ti++)
#pragma unroll
                for (int tj = 0; tj < 4; tj++)
                    wmma::store_matrix_sync(&stg[((wm & 1) * 32 + ti * 16) * LDST + wn * 64 + tj * 16],
                                            acc[ti][tj], LDST, wmma::mem_row_major);
        }
        __syncthreads();
#pragma unroll
        for (int i = tid; i < 2048; i += 256) {
            int r = i >> 5, c4 = (i & 31) * 4;
            int m = row0 + ph * 64 + r;
            int col = col0 + c4;
            float4 vv = *(float4*)&stg[r * LDST + c4];
            float4 bi = *(const float4*)&bias[col];
            vv.x += bi.x; vv.y += bi.y; vv.z += bi.z; vv.w += bi.w;
            int b = m >> 10, s = m & 1023, h = col >> 6, d = col & 63;
            cvt_store4_h(C + (((size_t)b * Hc + h) * Sc + s) * 64 + d, vv);
        }
        __syncthreads();
    }
}

// ---------------------------------------------------------------------------
// Scores (single fp16): 64x64 tile per block, mask -> raw fp32 scores.
// smem ~18KB -> high occupancy.
// ---------------------------------------------------------------------------
__global__ __launch_bounds__(256)
void scores_half(const __half* __restrict__ Qp, const __half* __restrict__ Kp,
                 const void* __restrict__ mask, float* __restrict__ attn) {
    constexpr int LDT = 72;
    constexpr int LDST = 68;

    __shared__ __align__(16) char buf[18688];
    __half* Qs = (__half*)buf;          // [64][72]
    __half* Ks = Qs + 64 * LDT;
    float* stg = (float*)buf;           // [64][68] epilogue reuse

    const int z = blockIdx.z;
    const int b = z >> 4;
    const int q0 = blockIdx.y * 64;
    const int k0 = blockIdx.x * 64;
    const int tid = threadIdx.x;
    const int w = tid >> 5;
    const int wm = w & 1;
    const int wn = w >> 1;

    const size_t zb = (size_t)z * Sc * 64;

#pragma unroll
    for (int i = tid; i < 512; i += 256) {
        int r = i >> 3, c = (i & 7) * 8;
        *(uint4*)&Qs[r * LDT + c] = *(const uint4*)&Qp[zb + (size_t)(q0 + r) * 64 + c];
        *(uint4*)&Ks[r * LDT + c] = *(const uint4*)&Kp[zb + (size_t)(k0 + r) * 64 + c];
    }
    __syncthreads();

    hfrag_c acc[2];
    wmma::fill_fragment(acc[0], 0.0f);
    wmma::fill_fragment(acc[1], 0.0f);

#pragma unroll
    for (int ks = 0; ks < 4; ks++) {
        const int kb = ks * 16;
        hfrag_a fa[2];
#pragma unroll
        for (int ti = 0; ti < 2; ti++)
            wmma::load_matrix_sync(fa[ti], Qs + (wm * 32 + ti * 16) * LDT + kb, LDT);
        hfrag_bc fb;
        wmma::load_matrix_sync(fb, Ks + (wn * 16) * LDT + kb, LDT);
#pragma unroll
        for (int ti = 0; ti < 2; ti++)
            wmma::mma_sync(acc[ti], fa[ti], fb, acc[ti]);
    }
    __syncthreads();
#pragma unroll
    for (int ti = 0; ti < 2; ti++)
        wmma::store_matrix_sync(&stg[(wm * 32 + ti * 16) * LDST + wn * 16], acc[ti],
                                LDST, wmma::mem_row_major);
    __syncthreads();

    const int mode = g_mask_mode;
    const int* mi = (const int*)mask;
    const unsigned char* mb8 = (const unsigned char*)mask;
    const float* mf = (const float*)mask;

#pragma unroll
    for (int i = tid; i < 4096; i += 256) {
        int r = i >> 6, c = i & 63;
        int qq = q0 + r, kk = k0 + c;
        size_t midx = (size_t)b * Sc * Sc + (size_t)qq * Sc + kk;
        bool masked;
        if (mode == 0)      masked = (mi[midx] != 0);
        else if (mode == 2) masked = (mf[midx] != 0.0f);
        else                masked = (mb8[midx] != 0);
        float v = masked ? -1e9f : stg[r * LDST + c] * 0.125f;
        attn[((size_t)z * Sc + qq) * Sc + kk] = v;
    }
}

// ---------------------------------------------------------------------------
// Row softmax, in place; also emits fp16 copy of probs for the context GEMM.
// ---------------------------------------------------------------------------
__global__ __launch_bounds__(256)
void softmax_kernel(float* __restrict__ attn, __half* __restrict__ attn_h) {
    const size_t row = blockIdx.x;
    float4* p = (float4*)(attn + row * Sc);
    __half* ph = attn_h + row * Sc;
    const int tid = threadIdx.x;
    const int lane = tid & 31, wid = tid >> 5;
    __shared__ float sm[16];

    float4 v = p[tid];
    float mx = fmaxf(fmaxf(v.x, v.y), fmaxf(v.z, v.w));
#pragma unroll
    for (int o = 16; o; o >>= 1) mx = fmaxf(mx, __shfl_xor_sync(0xffffffffu, mx, o));
    if (lane == 0) sm[wid] = mx;
    __syncthreads();
    float m = sm[0];
#pragma unroll
    for (int i = 1; i < 8; i++) m = fmaxf(m, sm[i]);

    v.x = expf(v.x - m); v.y = expf(v.y - m);
    v.z = expf(v.z - m); v.w = expf(v.w - m);
    float s = (v.x + v.y) + (v.z + v.w);
#pragma unroll
    for (int o = 16; o; o >>= 1) s += __shfl_xor_sync(0xffffffffu, s, o);
    if (lane == 0) sm[8 + wid] = s;
    __syncthreads();
    float tot = 0.0f;
#pragma unroll
    for (int i = 0; i < 8; i++) tot += sm[8 + i];
    float inv = 1.0f / tot;
    v.x *= inv; v.y *= inv; v.z *= inv; v.w *= inv;
    p[tid] = v;
    cvt_store4_h(ph + tid * 4, v);
}

// ---------------------------------------------------------------------------
// Context: BM=256, BN=64, single fp16, A = fp16 probs, warp tile 32x64.
// (R7-proven shape.)  Out: fp16 ctx plane, concat layout [B,S,1024].
// ---------------------------------------------------------------------------
__global__ __launch_bounds__(256)
void context_wide(const __half* __restrict__ P, const __half* __restrict__ Vp,
                  __half* __restrict__ C) {
    constexpr int LDA = 24;
    constexpr int LDW = 72;
    constexpr int LDST = 68;

    __shared__ __align__(16) char buf[34816];
    __half* As = (__half*)buf;          // [2][256][24]
    __half* Ws = As + 2 * 256 * LDA;    // [2][16][72]
    float* stg = (float*)buf;           // [128][68]

    const int tid = threadIdx.x;
    const int w = tid >> 5;
    const int z = blockIdx.y;
    const int row0 = blockIdx.x * 256;

    const __half* Pb = P + (size_t)z * Sc * Sc;
    const __half* Vb = Vp + (size_t)z * Sc * 64;

    const int ar = tid >> 1, ac = (tid & 1) * 8;
    const int in_b = tid < 128;
    const int wr = tid >> 3, wc = (tid & 7) * 8;

    hfrag_c acc[2][4];
#pragma unroll
    for (int ti = 0; ti < 2; ti++)
#pragma unroll
        for (int tj = 0; tj < 4; tj++) wmma::fill_fragment(acc[ti][tj], 0.0f);

    uint4 pa0, pa1, pb;
    pa0 = *(const uint4*)&Pb[(size_t)(row0 + ar) * Sc + ac];
    pa1 = *(const uint4*)&Pb[(size_t)(row0 + ar + 128) * Sc + ac];
    if (in_b) pb = *(const uint4*)&Vb[(size_t)wr * 64 + wc];
    *(uint4*)&As[ar * LDA + ac] = pa0;
    *(uint4*)&As[(ar + 128) * LDA + ac] = pa1;
    if (in_b) *(uint4*)&Ws[wr * LDW + wc] = pb;
    __syncthreads();

    for (int kt = 0; kt < 64; kt++) {
        if (kt < 63) {
            int kk = (kt + 1) * 16;
            pa0 = *(const uint4*)&Pb[(size_t)(row0 + ar) * Sc + kk + ac];
            pa1 = *(const uint4*)&Pb[(size_t)(row0 + ar + 128) * Sc + kk + ac];
            if (in_b) pb = *(const uint4*)&Vb[(size_t)(kk + wr) * 64 + wc];
        }
        const int cur = kt & 1;
        const int cb = cur * 256 * LDA;
        const int wb = cur * 16 * LDW;

        hfrag_a fa[2];
#pragma unroll
        for (int ti = 0; ti < 2; ti++)
            wmma::load_matrix_sync(fa[ti], As + cb + (w * 32 + ti * 16) * LDA, LDA);
#pragma unroll
        for (int tj = 0; tj < 4; tj++) {
            hfrag_b fb;
            wmma::load_matrix_sync(fb, Ws + wb + tj * 16, LDW);
#pragma unroll
            for (int ti = 0; ti < 2; ti++)
                wmma::mma_sync(acc[ti][tj], fa[ti], fb, acc[ti][tj]);
        }

        if (kt < 63) {
            const int nb = (cur ^ 1) * 256 * LDA;
            const int nw = (cur ^ 1) * 16 * LDW;
            *(uint4*)&As[nb + ar * LDA + ac] = pa0;
            *(uint4*)&As[nb + (ar + 128) * LDA + ac] = pa1;
            if (in_b) *(uint4*)&Ws[nw + wr * LDW + wc] = pb;
        }
        __syncthreads();
    }

    const int b = z >> 4, h = z & 15;
#pragma unroll
    for (int ph = 0; ph < 2; ph++) {
        if ((w >> 2) == ph) {
#pragma unroll
            for (int ti = 0; ti < 2; ti++)
#pragma unroll
                for (int tj = 0; tj < 4; tj++)
                    wmma::store_matrix_sync(&stg[((w & 3) * 32 + ti * 16) * LDST + tj * 16],
                                            acc[ti][tj], LDST, wmma::mem_row_major);
        }
        __syncthreads();
#pragma unroll
        for (int i = tid; i < 2048; i += 256) {
            int r = i >> 4, c4 = (i & 15) * 4;
            int s = row0 + ph * 128 + r;
            float4 vv = *(float4*)&stg[r * LDST + c4];
            cvt_store4_h(C + ((size_t)(b * Sc + s)) * HDc + h * DVc + c4, vv);
        }
        __syncthreads();
    }
}

// ---------------------------------------------------------------------------
// Out-proj: BM=128, BN=128, single fp16, A = ctx fp16 plane, fp32 out.
// (R7-proven shape.)
// ---------------------------------------------------------------------------
__global__ __launch_bounds__(256)
void outproj_wide(const __half* __restrict__ Ab, const float* __restrict__ W,
                  const float* __restrict__ bias, float* __restrict__ Cf) {
    constexpr int LDA = 24;
    constexpr int LDW = 136;
    constexpr int LDST = 132;

    __shared__ __align__(16) char buf[33792];
    __half* As = (__half*)buf;
    __half* Ws = As + 2 * 128 * LDA;
    float* stg = (float*)buf;

    const int tid = threadIdx.x;
    const int w = tid >> 5;
    const int wm = w >> 1;
    const int wn = w & 1;
    const int row0 = blockIdx.y * 128;
    const int col0 = blockIdx.x * 128;

    const int br = tid >> 1, bc = (tid & 1) * 8;
    const int wr0 = tid >> 5, wc0 = (tid & 31) * 4;

    hfrag_c acc[2][4];
#pragma unroll
    for (int ti = 0; ti < 2; ti++)
#pragma unroll
        for (int tj = 0; tj < 4; tj++) wmma::fill_fragment(acc[ti][tj], 0.0f);

    uint4 pa;
    float4 rw0, rw1;
    pa = *(const uint4*)&Ab[(size_t)(row0 + br) * Dc + bc];
    rw0 = *(const float4*)&W[(size_t)wr0 * Dc + col0 + wc0];
    rw1 = *(const float4*)&W[(size_t)(wr0 + 8) * Dc + col0 + wc0];
    *(uint4*)&As[br * LDA + bc] = pa;
    cvt_store4_h(Ws + wr0 * LDW + wc0, rw0);
    cvt_store4_h(Ws + (wr0 + 8) * LDW + wc0, rw1);
    __syncthreads();

    for (int kt = 0; kt < 64; kt++) {
        if (kt < 63) {
            int kk = (kt + 1) * 16;
            pa = *(const uint4*)&Ab[(size_t)(row0 + br) * Dc + kk + bc];
            rw0 = *(const float4*)&W[(size_t)(kk + wr0) * Dc + col0 + wc0];
            rw1 = *(const float4*)&W[(size_t)(kk + wr0 + 8) * Dc + col0 + wc0];
        }
        const int cur = kt & 1;
        const int cb = cur * 128 * LDA;
        const int wb = cur * 16 * LDW;

        hfrag_a fa[2];
#pragma unroll
        for (int ti = 0; ti < 2; ti++)
            wmma::load_matrix_sync(fa[ti], As + cb + (wm * 32 + ti * 16) * LDA, LDA);
#pragma unroll
        for (int tj = 0; tj < 4; tj++) {
            hfrag_b fb;
            wmma::load_matrix_sync(fb, Ws + wb + wn * 64 + tj * 16, LDW);
#pragma unroll
            for (int ti = 0; ti < 2; ti++)
                wmma::mma_sync(acc[ti][tj], fa[ti], fb, acc[ti][tj]);
        }

        if (kt < 63) {
            const int nb = (cur ^ 1) * 128 * LDA;
            const int nw = (cur ^ 1) * 16 * LDW;
            *(uint4*)&As[nb + br * LDA + bc] = pa;
            cvt_store4_h(Ws + nw + wr0 * LDW + wc0, rw0);
            cvt_store4_h(Ws + nw + (wr0 + 8) * LDW + wc0, rw1);
        }
        __syncthreads();
    }

#pragma unroll
    for (int ph = 0; ph < 2; ph++) {
        if ((wm >> 1) == ph) {
#pragma unroll
            for (int ti = 0; ti < 2; ti++)
#pragma unroll
                for (int tj = 0; tj < 4; tj++)
                    wmma::store_matrix_sync(&stg[((wm & 1) * 32 + ti * 16) * LDST + wn * 64 + tj * 16],
                                            acc[ti][tj], LDST, wmma::mem_row_major);
        }
        __syncthreads();
#pragma unroll
        for (int i = tid; i < 2048; i += 256) {
            int r = i >> 5, c4 = (i & 31) * 4;
            int m = row0 + ph * 64 + r;
            int col = col0 + c4;
            float4 vv = *(float4*)&stg[r * LDST + c4];
            float4 bi = *(const float4*)&bias[col];
            vv.x += bi.x; vv.y += bi.y; vv.z += bi.z; vv.w += bi.w;
            *(float4*)&Cf[(size_t)m * Dc + col] = vv;
        }
        __syncthreads();
    }
}

// ---------------------------------------------------------------------------
// Fused residual add + LayerNorm
// ---------------------------------------------------------------------------
__global__ __launch_bounds__(256)
void layernorm_kernel(const float* __restrict__ x, const float* __restrict__ resid,
                      float* __restrict__ out) {
    const size_t row = blockIdx.x;
    const float4* xr = (const float4*)(x + row * Dc);
    const float4* rr = (const float4*)(resid + row * Dc);
    float4* orow = (float4*)(out + row * Dc);
    const int tid = threadIdx.x;
    const int lane = tid & 31, wid = tid >> 5;
    __shared__ float sm[16];

    float4 a = xr[tid], b = rr[tid];
    float4 v = make_float4(a.x + b.x, a.y + b.y, a.z + b.z, a.w + b.w);
    float s = (v.x + v.y) + (v.z + v.w);
#pragma unroll
    for (int o = 16; o; o >>= 1) s += __shfl_xor_sync(0xffffffffu, s, o);
    if (lane == 0) sm[wid] = s;
    __syncthreads();
    float tot = 0.0f;
#pragma unroll
    for (int i = 0; i < 8; i++) tot += sm[i];
    float mean = tot * (1.0f / 1024.0f);

    float dx = v.x - mean, dy = v.y - mean, dz = v.z - mean, dw = v.w - mean;
    float vs = (dx * dx + dy * dy) + (dz * dz + dw * dw);
#pragma unroll
    for (int o = 16; o; o >>= 1) vs += __shfl_xor_sync(0xffffffffu, vs, o);
    if (lane == 0) sm[8 + wid] = vs;
    __syncthreads();
    float vtot = 0.0f;
#pragma unroll
    for (int i = 0; i < 8; i++) vtot += sm[8 + i];
    float inv = rsqrtf(vtot * (1.0f / 1024.0f) + 1e-5f);
    orow[tid] = make_float4(dx * inv, dy * inv, dz * inv, dw * inv);
}

// ---------------------------------------------------------------------------
// Launch
// ---------------------------------------------------------------------------
extern "C" void kernel_launch(void* const* d_in, const int* in_sizes, int n_in,
                              void* d_out, int out_size) {
    const float* q    = (const float*)d_in[0];
    const float* k    = (const float*)d_in[1];
    const float* v    = (const float*)d_in[2];
    const void*  mask = d_in[3];
    const float* Wq   = (const float*)d_in[4];
    const float* bq   = (const float*)d_in[5];
    const float* Wk   = (const float*)d_in[6];
    const float* bk   = (const float*)d_in[7];
    const float* Wv   = (const float*)d_in[8];
    const float* bv   = (const float*)d_in[9];
    const float* Wo   = (const float*)d_in[10];
    const float* bo   = (const float*)d_in[11];
    float* out = (float*)d_out;

    __half *Qp, *Kp, *Vp, *ctx, *attn_h;
    float *obuf, *attn_fb;
    cudaGetSymbolAddress((void**)&Qp, g_Qp);
    cudaGetSymbolAddress((void**)&Kp, g_Kp);
    cudaGetSymbolAddress((void**)&Vp, g_Vp);
    cudaGetSymbolAddress((void**)&ctx, g_ctx);
    cudaGetSymbolAddress((void**)&attn_h, g_attn_h);
    cudaGetSymbolAddress((void**)&obuf, g_obuf);
    cudaGetSymbolAddress((void**)&attn_fb, g_attn_fb);

    const long long LN_ELEMS = (long long)Mc * Dc;
    const long long ATTN_ELEMS = (long long)Bc * Hc * Sc * Sc;
    float* attn = ((long long)out_size >= LN_ELEMS + ATTN_ELEMS)
                      ? (out + (size_t)LN_ELEMS)
                      : attn_fb;

    detect_mask_kernel<<<1, 1>>>((const unsigned int*)mask);

    // Merged QKV projections, single fp16 (z: 0=Q, 1=K, 2=V)
    qkv_proj<<<dim3(8, 32, 3), 256>>>(q, k, v, Wq, Wk, Wv, bq, bk, bv, Qp, Kp, Vp);

    // Scores + mask -> raw fp32 scores (single fp16 MMA, high occupancy)
    scores_half<<<dim3(16, 16, Bc * Hc), 256>>>(Qp, Kp, mask, attn);

    // Softmax in place + fp16 probs copy
    softmax_kernel<<<Bc * Hc * Sc, 256>>>(attn, attn_h);

    // Context (fp16 probs @ fp16 V) -> fp16 ctx plane
    context_wide<<<dim3(4, 64), 256>>>(attn_h, Vp, ctx);

    // Output projection (fp16 A, fp32 out)
    outproj_wide<<<dim3(8, 32), 256>>>(ctx, Wo, bo, obuf);

    // Residual + LayerNorm
    layernorm_kernel<<<Mc, 256>>>(obuf, q, out);
}